// round 15
// baseline (speedup 1.0000x reference)
#include <cuda_runtime.h>
#include <cuda_fp16.h>
#include <cstdint>
#include <cstdio>

// Problem dims (fixed by the reference)
#define BATCH 4
#define SEQ   2048
#define DIM   1024
#define NHEAD 16
#define HDIM  64
#define FFD   4096
#define MROWS (BATCH*SEQ)   // 8192

// ---------------- scratch (static device globals; no runtime alloc) -------
__device__ __half g_h   [(size_t)MROWS * DIM];   // ln out (fp16)
__device__ __half g_q   [(size_t)MROWS * DIM];   // fp16 q/k/v
__device__ __half g_k   [(size_t)MROWS * DIM];
__device__ __half g_v   [(size_t)MROWS * DIM];
__device__ __half g_attn[(size_t)MROWS * DIM];   // fp16 (feeds WO gemm)
__device__ float  g_x1  [(size_t)MROWS * DIM];   // fp32 residual
__device__ __half g_ff  [(size_t)MROWS * FFD];   // fp16 (feeds FF2 gemm)
// transposed + fp16 weight copies  WT[n][k] = half(W[k][n])
__device__ __half g_wq_t[(size_t)DIM * DIM];
__device__ __half g_wk_t[(size_t)DIM * DIM];
__device__ __half g_wv_t[(size_t)DIM * DIM];
__device__ __half g_wo_t[(size_t)DIM * DIM];
__device__ __half g_w1_t[(size_t)DIM * FFD];   // [4096][1024]
__device__ __half g_w2_t[(size_t)FFD * DIM];   // [1024][4096]

// ---------------- helpers -------------------------------------------------
// fp16 mma (fp32 accumulate)
__device__ __forceinline__ void mma_f16(float* c, const unsigned* a, const unsigned* b) {
    asm volatile(
        "mma.sync.aligned.m16n8k16.row.col.f32.f16.f16.f32 "
        "{%0,%1,%2,%3}, {%4,%5,%6,%7}, {%8,%9}, {%0,%1,%2,%3};"
        : "+f"(c[0]), "+f"(c[1]), "+f"(c[2]), "+f"(c[3])
        : "r"(a[0]), "r"(a[1]), "r"(a[2]), "r"(a[3]), "r"(b[0]), "r"(b[1]));
}
__device__ __forceinline__ void ldsm_x4(unsigned* r, uint32_t addr) {
    asm volatile("ldmatrix.sync.aligned.m8n8.x4.shared.b16 {%0,%1,%2,%3}, [%4];"
        : "=r"(r[0]), "=r"(r[1]), "=r"(r[2]), "=r"(r[3]) : "r"(addr));
}
__device__ __forceinline__ void ldsm_x2(unsigned* r, uint32_t addr) {
    asm volatile("ldmatrix.sync.aligned.m8n8.x2.shared.b16 {%0,%1}, [%2];"
        : "=r"(r[0]), "=r"(r[1]) : "r"(addr));
}
__device__ __forceinline__ void ldsm_x2_t(unsigned* r, uint32_t addr) {
    asm volatile("ldmatrix.sync.aligned.m8n8.x2.trans.shared.b16 {%0,%1}, [%2];"
        : "=r"(r[0]), "=r"(r[1]) : "r"(addr));
}
__device__ __forceinline__ unsigned packh2(float a, float b) {
    __half2 h = __floats2half2_rn(a, b);
    return *(unsigned*)&h;
}
__device__ __forceinline__ void cpasync16(void* smem, const void* gmem) {
    unsigned s = (unsigned)__cvta_generic_to_shared(smem);
    asm volatile("cp.async.cg.shared.global [%0], [%1], 16;" :: "r"(s), "l"(gmem));
}
__device__ __forceinline__ void cpcommit() {
    asm volatile("cp.async.commit_group;");
}
template<int N> __device__ __forceinline__ void cpwait() {
    asm volatile("cp.async.wait_group %0;" :: "n"(N));
}
__device__ __forceinline__ uint32_t smem_u32(const void* p) {
    return (uint32_t)__cvta_generic_to_shared(p);
}

// ---------------- weight transpose + fp16 convert -------------------------
// S[R][C] float -> D[C][R] half (one matrix)
__global__ __launch_bounds__(256) void trh_kernel(
    const float* __restrict__ S, __half* __restrict__ D, int R, int C)
{
    __shared__ float t[32][33];
    int bx = blockIdx.x * 32;
    int by = blockIdx.y * 32;
    int tx = threadIdx.x & 31, ty = threadIdx.x >> 5;
    #pragma unroll
    for (int i = 0; i < 4; ++i) {
        int r = by + ty + i * 8;
        t[ty + i * 8][tx] = S[(size_t)r * C + bx + tx];
    }
    __syncthreads();
    #pragma unroll
    for (int i = 0; i < 4; ++i) {
        int r = bx + ty + i * 8;
        D[(size_t)r * R + by + tx] = __float2half(t[tx][ty + i * 8]);
    }
}

// batched version for the 4 DxD matrices (wq, wk, wv, wo)
__global__ __launch_bounds__(256) void trh4_kernel(
    const float* __restrict__ s0, __half* __restrict__ d0,
    const float* __restrict__ s1, __half* __restrict__ d1,
    const float* __restrict__ s2, __half* __restrict__ d2,
    const float* __restrict__ s3, __half* __restrict__ d3)
{
    const float* S; __half* D;
    switch (blockIdx.z) {
        case 0: S = s0; D = d0; break;
        case 1: S = s1; D = d1; break;
        case 2: S = s2; D = d2; break;
        default:S = s3; D = d3; break;
    }
    __shared__ float t[32][33];
    int bx = blockIdx.x * 32;
    int by = blockIdx.y * 32;
    int tx = threadIdx.x & 31, ty = threadIdx.x >> 5;
    #pragma unroll
    for (int i = 0; i < 4; ++i) {
        int r = by + ty + i * 8;
        t[ty + i * 8][tx] = S[(size_t)r * DIM + bx + tx];
    }
    __syncthreads();
    #pragma unroll
    for (int i = 0; i < 4; ++i) {
        int r = bx + ty + i * 8;
        D[(size_t)r * DIM + by + tx] = __float2half(t[tx][ty + i * 8]);
    }
}

// ---------------- layernorm (fp16 output) ---------------------------------
__global__ __launch_bounds__(256) void ln_kernel(
    const float* __restrict__ X, const float* __restrict__ gamma,
    const float* __restrict__ beta, __half* __restrict__ Y)
{
    int row = blockIdx.x;
    const float* x = X + (size_t)row * DIM;
    float4 v = *(const float4*)(x + threadIdx.x * 4);
    float s  = v.x + v.y + v.z + v.w;
    float ss = v.x*v.x + v.y*v.y + v.z*v.z + v.w*v.w;

    #pragma unroll
    for (int o = 16; o; o >>= 1) {
        s  += __shfl_xor_sync(0xffffffffu, s, o);
        ss += __shfl_xor_sync(0xffffffffu, ss, o);
    }
    __shared__ float sw[8], ssw[8], bc[2];
    int w = threadIdx.x >> 5, lane = threadIdx.x & 31;
    if (lane == 0) { sw[w] = s; ssw[w] = ss; }
    __syncthreads();
    if (threadIdx.x == 0) {
        float S = 0.f, SS = 0.f;
        #pragma unroll
        for (int i = 0; i < 8; ++i) { S += sw[i]; SS += ssw[i]; }
        float mu  = S * (1.f / DIM);
        float var = SS * (1.f / DIM) - mu * mu;
        bc[0] = mu;
        bc[1] = rsqrtf(var + 1e-5f);
    }
    __syncthreads();
    float mu = bc[0], r = bc[1];
    float4 gv = *(const float4*)(gamma + threadIdx.x * 4);
    float4 bv = *(const float4*)(beta  + threadIdx.x * 4);
    __half* yp = Y + (size_t)row * DIM + threadIdx.x * 4;
    *(__half2*)(yp)     = __floats2half2_rn((v.x - mu) * r * gv.x + bv.x,
                                            (v.y - mu) * r * gv.y + bv.y);
    *(__half2*)(yp + 2) = __floats2half2_rn((v.z - mu) * r * gv.z + bv.z,
                                            (v.w - mu) * r * gv.w + bv.w);
}

// ---------------- fp16 tensor-core GEMM, 3-stage cp.async, BK=64 ----------
// C[M,N] = A[M,K] @ BT[N,K]^T (+bias)(+res)(relu); OUT: 0=f32, 2=f16
constexpr int HSTRIDE = 72;                       // halfs per smem row (64+8 pad)
constexpr int ASZH = 128 * HSTRIDE;               // 9216 halfs per A stage
constexpr int STGH = 2 * ASZH;                    // halfs per stage (A+B)
constexpr int GEMM_SMEM = 3 * STGH * 2;           // 110592 bytes

__device__ __forceinline__ void load_tile_h(
    __half* sA, __half* sB, const __half* Ablk, const __half* Bblk,
    int k0, int K, int tid)
{
    // A tile: 128 rows x 64 halfs = 1024 16B-chunks; 4 per thread
    #pragma unroll
    for (int it = 0; it < 4; ++it) {
        int i = tid + it * 256;
        int r = i >> 3, c = i & 7;
        cpasync16(sA + r * HSTRIDE + c * 8, Ablk + (size_t)r * K + k0 + c * 8);
    }
    #pragma unroll
    for (int it = 0; it < 4; ++it) {
        int i = tid + it * 256;
        int r = i >> 3, c = i & 7;
        cpasync16(sB + r * HSTRIDE + c * 8, Bblk + (size_t)r * K + k0 + c * 8);
    }
}

template<bool HAS_BIAS, bool HAS_RES, bool RELU, int OUT>
__global__ __launch_bounds__(256, 2) void gemm_h(
    const __half* __restrict__ A, const __half* __restrict__ BT,
    const float* __restrict__ bias, const float* __restrict__ Res,
    void* __restrict__ Cv, int M, int N, int K)
{
    extern __shared__ __half smem[];

    int tid  = threadIdx.x;
    int warp = tid >> 5, lane = tid & 31;
    int wm = (warp >> 2) * 64;
    int wn = (warp & 3) * 32;
    int lg = lane >> 2;
    int lt = lane & 3;
    int bm = blockIdx.y, bn = blockIdx.x;

    const __half* Ablk = A  + (size_t)bm * 128 * K;
    const __half* Bblk = BT + (size_t)bn * 128 * K;

    uint32_t base_u = smem_u32(smem);
    uint32_t a_off = (uint32_t)(wm + (lane & 15)) * 144 + ((lane >> 4) & 1) * 16;
    uint32_t b_off = (uint32_t)(128 + wn + (lane & 7)) * 144 + ((lane >> 3) & 1) * 16;

    float acc[4][4][4] = {};

    load_tile_h(smem, smem + ASZH, Ablk, Bblk, 0, K, tid);
    cpcommit();
    load_tile_h(smem + STGH, smem + STGH + ASZH, Ablk, Bblk, 64, K, tid);
    cpcommit();

    int T = K / 64;
    int s = 0;
    for (int t = 0; t < T; ++t) {
        cpwait<1>();
        __syncthreads();
        uint32_t stage_u = base_u + s * (STGH * 2);

        #pragma unroll
        for (int ks = 0; ks < 4; ++ks) {
            unsigned a[4][4], b[4][2];
            #pragma unroll
            for (int mi = 0; mi < 4; ++mi)
                ldsm_x4(a[mi], stage_u + a_off + mi * (16 * 144) + ks * 32);
            #pragma unroll
            for (int ni = 0; ni < 4; ++ni)
                ldsm_x2(b[ni], stage_u + b_off + ni * (8 * 144) + ks * 32);
            #pragma unroll
            for (int mi = 0; mi < 4; ++mi)
                #pragma unroll
                for (int ni = 0; ni < 4; ++ni)
                    mma_f16(acc[mi][ni], a[mi], b[ni]);
        }
        int nt = t + 2;
        if (nt < T) {
            int sn = nt % 3;
            load_tile_h(smem + sn * STGH, smem + sn * STGH + ASZH,
                        Ablk, Bblk, nt * 64, K, tid);
        }
        cpcommit();
        s = (s + 1 == 3) ? 0 : s + 1;
    }

    #pragma unroll
    for (int mi = 0; mi < 4; ++mi) {
        int r0 = bm * 128 + wm + mi * 16 + lg;
        #pragma unroll
        for (int ni = 0; ni < 4; ++ni) {
            int c0 = bn * 128 + wn + ni * 8 + lt * 2;
            #pragma unroll
            for (int half_i = 0; half_i < 2; ++half_i) {
                int row = r0 + half_i * 8;
                float2 o;
                o.x = acc[mi][ni][half_i * 2 + 0];
                o.y = acc[mi][ni][half_i * 2 + 1];
                if (HAS_BIAS) { o.x += bias[c0]; o.y += bias[c0 + 1]; }
                if (HAS_RES) {
                    float2 rr = *(const float2*)(Res + (size_t)row * N + c0);
                    o.x += rr.x; o.y += rr.y;
                }
                if (RELU) { o.x = fmaxf(o.x, 0.f); o.y = fmaxf(o.y, 0.f); }
                if (OUT == 2) {
                    *(__half2*)((__half*)Cv + (size_t)row * N + c0) =
                        __floats2half2_rn(o.x, o.y);
                } else {
                    *(float2*)((float*)Cv + (size_t)row * N + c0) = o;
                }
            }
        }
    }
}

// ---------------- fp16 tensor-core causal flash attention -----------------
// 256 threads = 8 warps; Q tile = 128 queries; warp w owns rows [w*16,w*16+16).
// K tiles (64 keys) double-buffered via cp.async; V single buffer issued at
// tile top, awaited pre-PV. Halves K/V traffic vs 64-query tiles.
constexpr int AST = 72;   // halfs per attn smem row (144B) — conflict-free ldsm

__global__ __launch_bounds__(256) void attn_h(
    const __half* __restrict__ Q, const __half* __restrict__ Kg,
    const __half* __restrict__ Vg, __half* __restrict__ O)
{
    __shared__ __half Qs[128][AST];
    __shared__ __half Ks[2][64][AST];
    __shared__ __half Vs[64][AST];

    int tid = threadIdx.x;
    int w = tid >> 5, lane = tid & 31;
    int lg = lane >> 2, lt = lane & 3;
    int qt = blockIdx.x, h = blockIdx.y, b = blockIdx.z;
    size_t base = ((size_t)b * SEQ) * DIM + h * HDIM;

    // ---- prefetch K tile 0 (async) ----
    #pragma unroll
    for (int it = 0; it < 2; ++it) {
        int i = tid + it * 256;
        int r = i >> 3, c = i & 7;
        cpasync16(&Ks[0][r][c * 8], Kg + base + (size_t)r * DIM + c * 8);
    }
    cpcommit();

    // ---- stage Q tile: 128 rows (scaled by 1/8, exact in fp16) ----
    {
        __half2 sc = __half2half2(__float2half(0.125f));
        #pragma unroll
        for (int it = 0; it < 4; ++it) {
            int i = tid + it * 256;
            int r = i >> 3, c = i & 7;
            uint4 raw = *(const uint4*)(Q + base + (size_t)(qt * 128 + r) * DIM + c * 8);
            __half2* hp = (__half2*)&raw;
            hp[0] = __hmul2(hp[0], sc); hp[1] = __hmul2(hp[1], sc);
            hp[2] = __hmul2(hp[2], sc); hp[3] = __hmul2(hp[3], sc);
            *(uint4*)&Qs[r][c * 8] = raw;
        }
    }
    __syncthreads();
    unsigned qa[4][4];
    {
        uint32_t qaddr = smem_u32(&Qs[0][0])
                       + (uint32_t)(w * 16 + (lane & 15)) * (AST * 2)
                       + ((lane >> 4) & 1) * 16;
        #pragma unroll
        for (int ks = 0; ks < 4; ++ks) ldsm_x4(qa[ks], qaddr + ks * 32);
    }

    uint32_t v_base = smem_u32(&Vs[0][0]);
    uint32_t vfrag = v_base + (uint32_t)(lane & 15) * (AST * 2);

    float m0 = -1e30f, m1 = -1e30f, l0 = 0.f, l1 = 0.f;
    float oacc[8][4] = {};

    int KT = 2 * qt + 1;   // last k-tile index
    for (int kt = 0; kt <= KT; ++kt) {
        int cur = kt & 1;
        // ---- wait K(kt) (only pending group), barrier also frees Vs ----
        cpwait<0>();
        __syncthreads();

        // ---- issue V(kt) async (consumed after softmax) ----
        #pragma unroll
        for (int it = 0; it < 2; ++it) {
            int i = tid + it * 256;
            int r = i >> 3, c = i & 7;
            cpasync16(&Vs[r][c * 8],
                      Vg + base + (size_t)(kt * 64 + r) * DIM + c * 8);
        }
        cpcommit();

        uint32_t kfrag = smem_u32(&Ks[cur][0][0])
                       + (uint32_t)(lane & 7) * (AST * 2) + ((lane >> 3) & 1) * 16;

        // ---- S = Q K^T (16x64 per warp), 32 mmas ----
        float sacc[8][4] = {};
        #pragma unroll
        for (int ks = 0; ks < 4; ++ks) {
            unsigned bf[8][2];
            #pragma unroll
            for (int ni = 0; ni < 8; ++ni)
                ldsm_x2(bf[ni], kfrag + (uint32_t)ni * (8 * AST * 2) + ks * 32);
            #pragma unroll
            for (int ni = 0; ni < 8; ++ni)
                mma_f16(sacc[ni], qa[ks], bf[ni]);
        }

        // ---- prefetch K(kt+1) into the other buffer ----
        if (kt < KT) {
            int nb = cur ^ 1;
            #pragma unroll
            for (int it = 0; it < 2; ++it) {
                int i = tid + it * 256;
                int r = i >> 3, c = i & 7;
                cpasync16(&Ks[nb][r][c * 8],
                          Kg + base + (size_t)((kt + 1) * 64 + r) * DIM + c * 8);
            }
            cpcommit();
        }

        // ---- causal mask (last two k-tiles; global indices) ----
        if (kt >= 2 * qt) {
            int rq0 = qt * 128 + w * 16 + lg, rq1 = rq0 + 8;
            int jb = kt * 64;
            #pragma unroll
            for (int ni = 0; ni < 8; ++ni) {
                int j0 = jb + ni * 8 + 2 * lt, j1 = j0 + 1;
                if (j0 > rq0) sacc[ni][0] = -1e30f;
                if (j1 > rq0) sacc[ni][1] = -1e30f;
                if (j0 > rq1) sacc[ni][2] = -1e30f;
                if (j1 > rq1) sacc[ni][3] = -1e30f;
            }
        }

        // ---- online softmax ----
        float mx0 = -1e30f, mx1 = -1e30f;
        #pragma unroll
        for (int ni = 0; ni < 8; ++ni) {
            mx0 = fmaxf(mx0, fmaxf(sacc[ni][0], sacc[ni][1]));
            mx1 = fmaxf(mx1, fmaxf(sacc[ni][2], sacc[ni][3]));
        }
        mx0 = fmaxf(mx0, __shfl_xor_sync(0xffffffffu, mx0, 1));
        mx0 = fmaxf(mx0, __shfl_xor_sync(0xffffffffu, mx0, 2));
        mx1 = fmaxf(mx1, __shfl_xor_sync(0xffffffffu, mx1, 1));
        mx1 = fmaxf(mx1, __shfl_xor_sync(0xffffffffu, mx1, 2));
        float m0n = fmaxf(m0, mx0), m1n = fmaxf(m1, mx1);
        float c0 = __expf(m0 - m0n), c1 = __expf(m1 - m1n);
        l0 *= c0; l1 *= c1;
        #pragma unroll
        for (int ni = 0; ni < 8; ++ni) {
            oacc[ni][0] *= c0; oacc[ni][1] *= c0;
            oacc[ni][2] *= c1; oacc[ni][3] *= c1;
        }
        m0 = m0n; m1 = m1n;

        // ---- P = exp(S-m) directly into A-fragment registers ----
        unsigned pa[4][4];
        {
            float ps0 = 0.f, ps1 = 0.f;
            #pragma unroll
            for (int nj = 0; nj < 4; ++nj) {
                float e00 = __expf(sacc[2*nj][0] - m0n);
                float e01 = __expf(sacc[2*nj][1] - m0n);
                float e02 = __expf(sacc[2*nj][2] - m1n);
                float e03 = __expf(sacc[2*nj][3] - m1n);
                float e10 = __expf(sacc[2*nj+1][0] - m0n);
                float e11 = __expf(sacc[2*nj+1][1] - m0n);
                float e12 = __expf(sacc[2*nj+1][2] - m1n);
                float e13 = __expf(sacc[2*nj+1][3] - m1n);
                ps0 += e00 + e01 + e10 + e11;
                ps1 += e02 + e03 + e12 + e13;
                pa[nj][0] = packh2(e00, e01);   // row lg,   k low
                pa[nj][1] = packh2(e02, e03);   // row lg+8, k low
                pa[nj][2] = packh2(e10, e11);   // row lg,   k high
                pa[nj][3] = packh2(e12, e13);   // row lg+8, k high
            }
            l0 += ps0; l1 += ps1;
        }

        // ---- wait V(kt): leave K(kt+1) in flight when present ----
        if (kt < KT) cpwait<1>(); else cpwait<0>();
        __syncthreads();

        // ---- O += P V  (32 mmas, V via ldmatrix.trans) ----
        #pragma unroll
        for (int nj = 0; nj < 4; ++nj) {
            unsigned vb[8][2];
            #pragma unroll
            for (int ni = 0; ni < 8; ++ni)
                ldsm_x2_t(vb[ni], vfrag + (uint32_t)nj * (16 * AST * 2) + ni * 16);
            #pragma unroll
            for (int ni = 0; ni < 8; ++ni)
                mma_f16(oacc[ni], pa[nj], vb[ni]);
        }
        // no extra barrier: next tile-top cpwait<0> + __syncthreads protects Vs
    }

    // ---- finalize ----
    l0 += __shfl_xor_sync(0xffffffffu, l0, 1);
    l0 += __shfl_xor_sync(0xffffffffu, l0, 2);
    l1 += __shfl_xor_sync(0xffffffffu, l1, 1);
    l1 += __shfl_xor_sync(0xffffffffu, l1, 2);
    float inv0 = 1.f / l0, inv1 = 1.f / l1;

    int r0 = qt * 128 + w * 16 + lg;
    #pragma unroll
    for (int ni = 0; ni < 8; ++ni) {
        int c = ni * 8 + 2 * lt;
        *(__half2*)(O + base + (size_t)r0 * DIM + c) =
            __floats2half2_rn(oacc[ni][0] * inv0, oacc[ni][1] * inv0);
        *(__half2*)(O + base + (size_t)(r0 + 8) * DIM + c) =
            __floats2half2_rn(oacc[ni][2] * inv1, oacc[ni][3] * inv1);
    }
}

// ---------------- launch ------------------------------------------------
extern "C" void kernel_launch(void* const* d_in, const int* in_sizes, int n_in,
                              void* d_out, int out_size)
{
    const float* x     = (const float*)d_in[0];
    const float* wq    = (const float*)d_in[1];
    const float* wk    = (const float*)d_in[2];
    const float* wv    = (const float*)d_in[3];
    const float* wo    = (const float*)d_in[4];
    const float* bo    = (const float*)d_in[5];
    const float* w1    = (const float*)d_in[6];
    const float* b1    = (const float*)d_in[7];
    const float* w2    = (const float*)d_in[8];
    const float* b2    = (const float*)d_in[9];
    const float* gln1  = (const float*)d_in[10];
    const float* bln1  = (const float*)d_in[11];
    const float* gln2  = (const float*)d_in[12];
    const float* bln2  = (const float*)d_in[13];
    float* out = (float*)d_out;

    __half *p_h, *p_q, *p_k, *p_v, *p_attn, *p_ff;
    __half *p_wq, *p_wk, *p_wv, *p_wo, *p_w1, *p_w2;
    float  *p_x1;
    cudaGetSymbolAddress((void**)&p_h,    g_h);
    cudaGetSymbolAddress((void**)&p_q,    g_q);
    cudaGetSymbolAddress((void**)&p_k,    g_k);
    cudaGetSymbolAddress((void**)&p_v,    g_v);
    cudaGetSymbolAddress((void**)&p_attn, g_attn);
    cudaGetSymbolAddress((void**)&p_x1,   g_x1);
    cudaGetSymbolAddress((void**)&p_ff,   g_ff);
    cudaGetSymbolAddress((void**)&p_wq,   g_wq_t);
    cudaGetSymbolAddress((void**)&p_wk,   g_wk_t);
    cudaGetSymbolAddress((void**)&p_wv,   g_wv_t);
    cudaGetSymbolAddress((void**)&p_wo,   g_wo_t);
    cudaGetSymbolAddress((void**)&p_w1,   g_w1_t);
    cudaGetSymbolAddress((void**)&p_w2,   g_w2_t);

    static bool attr_done = false;
    if (!attr_done) {
        cudaFuncSetAttribute(gemm_h<false,false,false,2>,
            cudaFuncAttributeMaxDynamicSharedMemorySize, GEMM_SMEM);
        cudaFuncSetAttribute(gemm_h<true,true,false,0>,
            cudaFuncAttributeMaxDynamicSharedMemorySize, GEMM_SMEM);
        cudaFuncSetAttribute(gemm_h<true,false,true,2>,
            cudaFuncAttributeMaxDynamicSharedMemorySize, GEMM_SMEM);
        attr_done = true;
    }

    dim3 gD(DIM / 128, MROWS / 128);   // (8, 64)
    dim3 gF(FFD / 128, MROWS / 128);   // (32, 64)

    // 0) transpose + fp16-convert all weights (4 DxD in one launch)
    trh4_kernel<<<dim3(DIM/32, DIM/32, 4), 256>>>(
        wq, p_wq, wk, p_wk, wv, p_wv, wo, p_wo);
    trh_kernel<<<dim3(FFD/32, DIM/32), 256>>>(w1, p_w1, DIM, FFD);
    trh_kernel<<<dim3(DIM/32, FFD/32), 256>>>(w2, p_w2, FFD, DIM);

    // 1) h = ln1(x)
    ln_kernel<<<MROWS, 256>>>(x, gln1, bln1, p_h);
    // 2) q,k,v = h @ W{q,k,v}  (fp16 outputs)
    gemm_h<false,false,false,2><<<gD, 256, GEMM_SMEM>>>(p_h, p_wq, nullptr, nullptr, p_q, MROWS, DIM, DIM);
    gemm_h<false,false,false,2><<<gD, 256, GEMM_SMEM>>>(p_h, p_wk, nullptr, nullptr, p_k, MROWS, DIM, DIM);
    gemm_h<false,false,false,2><<<gD, 256, GEMM_SMEM>>>(p_h, p_wv, nullptr, nullptr, p_v, MROWS, DIM, DIM);
    // 3) causal attention (fp16 mma; 128-query tiles; fp16 output)
    attn_h<<<dim3(SEQ / 128, NHEAD, BATCH), 256>>>(p_q, p_k, p_v, p_attn);
    // 4) x1 = x + attn @ wo + bo   (fp32 residual)
    gemm_h<true,true,false,0><<<gD, 256, GEMM_SMEM>>>(p_attn, p_wo, bo, x, p_x1, MROWS, DIM, DIM);
    // 5) h = ln2(x1)
    ln_kernel<<<MROWS, 256>>>(p_x1, gln2, bln2, p_h);
    // 6) ff = relu(h @ w1 + b1)  (fp16 output)
    gemm_h<true,false,true,2><<<gF, 256, GEMM_SMEM>>>(p_h, p_w1, b1, nullptr, p_ff, MROWS, FFD, DIM);
    // 7) out = x1 + ff @ w2 + b2  (fp32 final output)
    gemm_h<true,true,false,0><<<gD, 256, GEMM_SMEM>>>(p_ff, p_w2, b2, p_x1, out, MROWS, DIM, FFD);
}

// round 16
// speedup vs baseline: 1.0470x; 1.0470x over previous
#include <cuda_runtime.h>
#include <cuda_fp16.h>
#include <cstdint>
#include <cstdio>

// Problem dims (fixed by the reference)
#define BATCH 4
#define SEQ   2048
#define DIM   1024
#define NHEAD 16
#define HDIM  64
#define FFD   4096
#define MROWS (BATCH*SEQ)   // 8192

// ---------------- scratch (static device globals; no runtime alloc) -------
__device__ __half g_h   [(size_t)MROWS * DIM];   // ln out (fp16)
__device__ __half g_q   [(size_t)MROWS * DIM];   // fp16 q/k/v
__device__ __half g_k   [(size_t)MROWS * DIM];
__device__ __half g_v   [(size_t)MROWS * DIM];
__device__ __half g_attn[(size_t)MROWS * DIM];   // fp16 (feeds WO gemm)
__device__ float  g_x1  [(size_t)MROWS * DIM];   // fp32 residual
__device__ __half g_ff  [(size_t)MROWS * FFD];   // fp16 (feeds FF2 gemm)
// transposed + fp16 weight copies  WT[n][k] = half(W[k][n])
__device__ __half g_wq_t[(size_t)DIM * DIM];
__device__ __half g_wk_t[(size_t)DIM * DIM];
__device__ __half g_wv_t[(size_t)DIM * DIM];
__device__ __half g_wo_t[(size_t)DIM * DIM];
__device__ __half g_w1_t[(size_t)DIM * FFD];   // [4096][1024]
__device__ __half g_w2_t[(size_t)FFD * DIM];   // [1024][4096]

// ---------------- helpers -------------------------------------------------
// fp16 mma (fp32 accumulate)
__device__ __forceinline__ void mma_f16(float* c, const unsigned* a, const unsigned* b) {
    asm volatile(
        "mma.sync.aligned.m16n8k16.row.col.f32.f16.f16.f32 "
        "{%0,%1,%2,%3}, {%4,%5,%6,%7}, {%8,%9}, {%0,%1,%2,%3};"
        : "+f"(c[0]), "+f"(c[1]), "+f"(c[2]), "+f"(c[3])
        : "r"(a[0]), "r"(a[1]), "r"(a[2]), "r"(a[3]), "r"(b[0]), "r"(b[1]));
}
__device__ __forceinline__ void ldsm_x4(unsigned* r, uint32_t addr) {
    asm volatile("ldmatrix.sync.aligned.m8n8.x4.shared.b16 {%0,%1,%2,%3}, [%4];"
        : "=r"(r[0]), "=r"(r[1]), "=r"(r[2]), "=r"(r[3]) : "r"(addr));
}
__device__ __forceinline__ void ldsm_x2(unsigned* r, uint32_t addr) {
    asm volatile("ldmatrix.sync.aligned.m8n8.x2.shared.b16 {%0,%1}, [%2];"
        : "=r"(r[0]), "=r"(r[1]) : "r"(addr));
}
__device__ __forceinline__ void ldsm_x2_t(unsigned* r, uint32_t addr) {
    asm volatile("ldmatrix.sync.aligned.m8n8.x2.trans.shared.b16 {%0,%1}, [%2];"
        : "=r"(r[0]), "=r"(r[1]) : "r"(addr));
}
__device__ __forceinline__ unsigned packh2(float a, float b) {
    __half2 h = __floats2half2_rn(a, b);
    return *(unsigned*)&h;
}
__device__ __forceinline__ void cpasync16(void* smem, const void* gmem) {
    unsigned s = (unsigned)__cvta_generic_to_shared(smem);
    asm volatile("cp.async.cg.shared.global [%0], [%1], 16;" :: "r"(s), "l"(gmem));
}
__device__ __forceinline__ void cpcommit() {
    asm volatile("cp.async.commit_group;");
}
template<int N> __device__ __forceinline__ void cpwait() {
    asm volatile("cp.async.wait_group %0;" :: "n"(N));
}
__device__ __forceinline__ uint32_t smem_u32(const void* p) {
    return (uint32_t)__cvta_generic_to_shared(p);
}

// ---------------- weight transpose + fp16 convert -------------------------
// S[R][C] float -> D[C][R] half (one matrix)
__global__ __launch_bounds__(256) void trh_kernel(
    const float* __restrict__ S, __half* __restrict__ D, int R, int C)
{
    __shared__ float t[32][33];
    int bx = blockIdx.x * 32;
    int by = blockIdx.y * 32;
    int tx = threadIdx.x & 31, ty = threadIdx.x >> 5;
    #pragma unroll
    for (int i = 0; i < 4; ++i) {
        int r = by + ty + i * 8;
        t[ty + i * 8][tx] = S[(size_t)r * C + bx + tx];
    }
    __syncthreads();
    #pragma unroll
    for (int i = 0; i < 4; ++i) {
        int r = bx + ty + i * 8;
        D[(size_t)r * R + by + tx] = __float2half(t[tx][ty + i * 8]);
    }
}

// batched version for the 4 DxD matrices (wq, wk, wv, wo)
__global__ __launch_bounds__(256) void trh4_kernel(
    const float* __restrict__ s0, __half* __restrict__ d0,
    const float* __restrict__ s1, __half* __restrict__ d1,
    const float* __restrict__ s2, __half* __restrict__ d2,
    const float* __restrict__ s3, __half* __restrict__ d3)
{
    const float* S; __half* D;
    switch (blockIdx.z) {
        case 0: S = s0; D = d0; break;
        case 1: S = s1; D = d1; break;
        case 2: S = s2; D = d2; break;
        default:S = s3; D = d3; break;
    }
    __shared__ float t[32][33];
    int bx = blockIdx.x * 32;
    int by = blockIdx.y * 32;
    int tx = threadIdx.x & 31, ty = threadIdx.x >> 5;
    #pragma unroll
    for (int i = 0; i < 4; ++i) {
        int r = by + ty + i * 8;
        t[ty + i * 8][tx] = S[(size_t)r * DIM + bx + tx];
    }
    __syncthreads();
    #pragma unroll
    for (int i = 0; i < 4; ++i) {
        int r = bx + ty + i * 8;
        D[(size_t)r * DIM + by + tx] = __float2half(t[tx][ty + i * 8]);
    }
}

// ---------------- layernorm (fp16 output) ---------------------------------
__global__ __launch_bounds__(256) void ln_kernel(
    const float* __restrict__ X, const float* __restrict__ gamma,
    const float* __restrict__ beta, __half* __restrict__ Y)
{
    int row = blockIdx.x;
    const float* x = X + (size_t)row * DIM;
    float4 v = *(const float4*)(x + threadIdx.x * 4);
    float s  = v.x + v.y + v.z + v.w;
    float ss = v.x*v.x + v.y*v.y + v.z*v.z + v.w*v.w;

    #pragma unroll
    for (int o = 16; o; o >>= 1) {
        s  += __shfl_xor_sync(0xffffffffu, s, o);
        ss += __shfl_xor_sync(0xffffffffu, ss, o);
    }
    __shared__ float sw[8], ssw[8], bc[2];
    int w = threadIdx.x >> 5, lane = threadIdx.x & 31;
    if (lane == 0) { sw[w] = s; ssw[w] = ss; }
    __syncthreads();
    if (threadIdx.x == 0) {
        float S = 0.f, SS = 0.f;
        #pragma unroll
        for (int i = 0; i < 8; ++i) { S += sw[i]; SS += ssw[i]; }
        float mu  = S * (1.f / DIM);
        float var = SS * (1.f / DIM) - mu * mu;
        bc[0] = mu;
        bc[1] = rsqrtf(var + 1e-5f);
    }
    __syncthreads();
    float mu = bc[0], r = bc[1];
    float4 gv = *(const float4*)(gamma + threadIdx.x * 4);
    float4 bv = *(const float4*)(beta  + threadIdx.x * 4);
    __half* yp = Y + (size_t)row * DIM + threadIdx.x * 4;
    *(__half2*)(yp)     = __floats2half2_rn((v.x - mu) * r * gv.x + bv.x,
                                            (v.y - mu) * r * gv.y + bv.y);
    *(__half2*)(yp + 2) = __floats2half2_rn((v.z - mu) * r * gv.z + bv.z,
                                            (v.w - mu) * r * gv.w + bv.w);
}

// ---------------- fp16 tensor-core GEMM, 3-stage cp.async, BK=64 ----------
// C[M,N] = A[M,K] @ BT[N,K]^T (+bias)(+res)(relu); OUT: 0=f32, 2=f16
// B fragments fetched two n-groups at a time via ldmatrix.x4.
constexpr int HSTRIDE = 72;                       // halfs per smem row (64+8 pad)
constexpr int ASZH = 128 * HSTRIDE;               // 9216 halfs per A stage
constexpr int STGH = 2 * ASZH;                    // halfs per stage (A+B)
constexpr int GEMM_SMEM = 3 * STGH * 2;           // 110592 bytes

__device__ __forceinline__ void load_tile_h(
    __half* sA, __half* sB, const __half* Ablk, const __half* Bblk,
    int k0, int K, int tid)
{
    // A tile: 128 rows x 64 halfs = 1024 16B-chunks; 4 per thread
    #pragma unroll
    for (int it = 0; it < 4; ++it) {
        int i = tid + it * 256;
        int r = i >> 3, c = i & 7;
        cpasync16(sA + r * HSTRIDE + c * 8, Ablk + (size_t)r * K + k0 + c * 8);
    }
    #pragma unroll
    for (int it = 0; it < 4; ++it) {
        int i = tid + it * 256;
        int r = i >> 3, c = i & 7;
        cpasync16(sB + r * HSTRIDE + c * 8, Bblk + (size_t)r * K + k0 + c * 8);
    }
}

template<bool HAS_BIAS, bool HAS_RES, bool RELU, int OUT>
__global__ __launch_bounds__(256, 2) void gemm_h(
    const __half* __restrict__ A, const __half* __restrict__ BT,
    const float* __restrict__ bias, const float* __restrict__ Res,
    void* __restrict__ Cv, int M, int N, int K)
{
    extern __shared__ __half smem[];

    int tid  = threadIdx.x;
    int warp = tid >> 5, lane = tid & 31;
    int wm = (warp >> 2) * 64;
    int wn = (warp & 3) * 32;
    int lg = lane >> 2;
    int lt = lane & 3;
    int bm = blockIdx.y, bn = blockIdx.x;

    const __half* Ablk = A  + (size_t)bm * 128 * K;
    const __half* Bblk = BT + (size_t)bn * 128 * K;

    uint32_t base_u = smem_u32(smem);
    uint32_t a_off = (uint32_t)(wm + (lane & 15)) * 144 + ((lane >> 4) & 1) * 16;
    // B x4 layout: lanes 0-7 row n..n+7 (k lo), 8-15 same rows (k hi),
    //              16-23 rows n+8..n+15 (k lo), 24-31 (k hi)
    uint32_t b_off = (uint32_t)(128 + wn + (lane & 7) + ((lane >> 4) & 1) * 8) * 144
                   + ((lane >> 3) & 1) * 16;

    float acc[4][4][4] = {};

    load_tile_h(smem, smem + ASZH, Ablk, Bblk, 0, K, tid);
    cpcommit();
    load_tile_h(smem + STGH, smem + STGH + ASZH, Ablk, Bblk, 64, K, tid);
    cpcommit();

    int T = K / 64;
    int s = 0;
    for (int t = 0; t < T; ++t) {
        cpwait<1>();
        __syncthreads();
        uint32_t stage_u = base_u + s * (STGH * 2);

        #pragma unroll
        for (int ks = 0; ks < 4; ++ks) {
            unsigned a[4][4], b[4][2];
            #pragma unroll
            for (int mi = 0; mi < 4; ++mi)
                ldsm_x4(a[mi], stage_u + a_off + mi * (16 * 144) + ks * 32);
            #pragma unroll
            for (int nj = 0; nj < 2; ++nj) {
                unsigned bq[4];
                ldsm_x4(bq, stage_u + b_off + nj * (16 * 144) + ks * 32);
                b[2 * nj][0]     = bq[0];
                b[2 * nj][1]     = bq[1];
                b[2 * nj + 1][0] = bq[2];
                b[2 * nj + 1][1] = bq[3];
            }
            #pragma unroll
            for (int mi = 0; mi < 4; ++mi)
                #pragma unroll
                for (int ni = 0; ni < 4; ++ni)
                    mma_f16(acc[mi][ni], a[mi], b[ni]);
        }
        int nt = t + 2;
        if (nt < T) {
            int sn = nt % 3;
            load_tile_h(smem + sn * STGH, smem + sn * STGH + ASZH,
                        Ablk, Bblk, nt * 64, K, tid);
        }
        cpcommit();
        s = (s + 1 == 3) ? 0 : s + 1;
    }

    #pragma unroll
    for (int mi = 0; mi < 4; ++mi) {
        int r0 = bm * 128 + wm + mi * 16 + lg;
        #pragma unroll
        for (int ni = 0; ni < 4; ++ni) {
            int c0 = bn * 128 + wn + ni * 8 + lt * 2;
            #pragma unroll
            for (int half_i = 0; half_i < 2; ++half_i) {
                int row = r0 + half_i * 8;
                float2 o;
                o.x = acc[mi][ni][half_i * 2 + 0];
                o.y = acc[mi][ni][half_i * 2 + 1];
                if (HAS_BIAS) { o.x += bias[c0]; o.y += bias[c0 + 1]; }
                if (HAS_RES) {
                    float2 rr = *(const float2*)(Res + (size_t)row * N + c0);
                    o.x += rr.x; o.y += rr.y;
                }
                if (RELU) { o.x = fmaxf(o.x, 0.f); o.y = fmaxf(o.y, 0.f); }
                if (OUT == 2) {
                    *(__half2*)((__half*)Cv + (size_t)row * N + c0) =
                        __floats2half2_rn(o.x, o.y);
                } else {
                    *(float2*)((float*)Cv + (size_t)row * N + c0) = o;
                }
            }
        }
    }
}

// ---------------- fp16 tensor-core causal flash attention -----------------
// 128 threads = 4 warps; warp w owns query rows [w*16, w*16+16).
// K double-buffered via cp.async (prefetch during softmax/PV); V single
// buffer, issued at tile top and awaited only before PV. 2 barriers/tile.
constexpr int AST = 72;   // halfs per attn smem row (144B) — conflict-free ldsm

__global__ __launch_bounds__(128) void attn_h(
    const __half* __restrict__ Q, const __half* __restrict__ Kg,
    const __half* __restrict__ Vg, __half* __restrict__ O)
{
    __shared__ __half Qs[64][AST];
    __shared__ __half Ks[2][64][AST];
    __shared__ __half Vs[64][AST];

    int tid = threadIdx.x;
    int w = tid >> 5, lane = tid & 31;
    int lg = lane >> 2, lt = lane & 3;
    int qt = blockIdx.x, h = blockIdx.y, b = blockIdx.z;
    size_t base = ((size_t)b * SEQ) * DIM + h * HDIM;

    // ---- prefetch K tile 0 (async) ----
    #pragma unroll
    for (int it = 0; it < 4; ++it) {
        int i = tid + it * 128;
        int r = i >> 3, c = i & 7;
        cpasync16(&Ks[0][r][c * 8], Kg + base + (size_t)r * DIM + c * 8);
    }
    cpcommit();

    // ---- stage Q tile (scaled by 1/8, exact in fp16) ----
    {
        __half2 sc = __half2half2(__float2half(0.125f));
        #pragma unroll
        for (int it = 0; it < 4; ++it) {
            int i = tid + it * 128;
            int r = i >> 3, c = i & 7;
            uint4 raw = *(const uint4*)(Q + base + (size_t)(qt * 64 + r) * DIM + c * 8);
            __half2* hp = (__half2*)&raw;
            hp[0] = __hmul2(hp[0], sc); hp[1] = __hmul2(hp[1], sc);
            hp[2] = __hmul2(hp[2], sc); hp[3] = __hmul2(hp[3], sc);
            *(uint4*)&Qs[r][c * 8] = raw;
        }
    }
    __syncthreads();
    unsigned qa[4][4];
    {
        uint32_t qaddr = smem_u32(&Qs[0][0])
                       + (uint32_t)(w * 16 + (lane & 15)) * (AST * 2)
                       + ((lane >> 4) & 1) * 16;
        #pragma unroll
        for (int ks = 0; ks < 4; ++ks) ldsm_x4(qa[ks], qaddr + ks * 32);
    }

    uint32_t v_base = smem_u32(&Vs[0][0]);
    uint32_t vfrag = v_base + (uint32_t)(lane & 15) * (AST * 2);

    float m0 = -1e30f, m1 = -1e30f, l0 = 0.f, l1 = 0.f;
    float oacc[8][4] = {};

    for (int kt = 0; kt <= qt; ++kt) {
        int cur = kt & 1;
        // ---- wait K(kt) (only pending group), barrier also frees Vs ----
        cpwait<0>();
        __syncthreads();

        // ---- issue V(kt) async (consumed after softmax) ----
        #pragma unroll
        for (int it = 0; it < 4; ++it) {
            int i = tid + it * 128;
            int r = i >> 3, c = i & 7;
            cpasync16(&Vs[r][c * 8],
                      Vg + base + (size_t)(kt * 64 + r) * DIM + c * 8);
        }
        cpcommit();

        uint32_t kfrag = smem_u32(&Ks[cur][0][0])
                       + (uint32_t)(lane & 7) * (AST * 2) + ((lane >> 3) & 1) * 16;

        // ---- S = Q K^T (16x64 per warp), 32 mmas ----
        float sacc[8][4] = {};
        #pragma unroll
        for (int ks = 0; ks < 4; ++ks) {
            unsigned bf[8][2];
            #pragma unroll
            for (int ni = 0; ni < 8; ++ni)
                ldsm_x2(bf[ni], kfrag + (uint32_t)ni * (8 * AST * 2) + ks * 32);
            #pragma unroll
            for (int ni = 0; ni < 8; ++ni)
                mma_f16(sacc[ni], qa[ks], bf[ni]);
        }

        // ---- prefetch K(kt+1) into the other buffer ----
        if (kt < qt) {
            int nb = cur ^ 1;
            #pragma unroll
            for (int it = 0; it < 4; ++it) {
                int i = tid + it * 128;
                int r = i >> 3, c = i & 7;
                cpasync16(&Ks[nb][r][c * 8],
                          Kg + base + (size_t)((kt + 1) * 64 + r) * DIM + c * 8);
            }
            cpcommit();
        }

        // ---- causal mask (diagonal tile only) ----
        if (kt == qt) {
            int rq0 = w * 16 + lg, rq1 = rq0 + 8;
            #pragma unroll
            for (int ni = 0; ni < 8; ++ni) {
                int j0 = ni * 8 + 2 * lt, j1 = j0 + 1;
                if (j0 > rq0) sacc[ni][0] = -1e30f;
                if (j1 > rq0) sacc[ni][1] = -1e30f;
                if (j0 > rq1) sacc[ni][2] = -1e30f;
                if (j1 > rq1) sacc[ni][3] = -1e30f;
            }
        }

        // ---- online softmax ----
        float mx0 = -1e30f, mx1 = -1e30f;
        #pragma unroll
        for (int ni = 0; ni < 8; ++ni) {
            mx0 = fmaxf(mx0, fmaxf(sacc[ni][0], sacc[ni][1]));
            mx1 = fmaxf(mx1, fmaxf(sacc[ni][2], sacc[ni][3]));
        }
        mx0 = fmaxf(mx0, __shfl_xor_sync(0xffffffffu, mx0, 1));
        mx0 = fmaxf(mx0, __shfl_xor_sync(0xffffffffu, mx0, 2));
        mx1 = fmaxf(mx1, __shfl_xor_sync(0xffffffffu, mx1, 1));
        mx1 = fmaxf(mx1, __shfl_xor_sync(0xffffffffu, mx1, 2));
        float m0n = fmaxf(m0, mx0), m1n = fmaxf(m1, mx1);
        float c0 = __expf(m0 - m0n), c1 = __expf(m1 - m1n);
        l0 *= c0; l1 *= c1;
        #pragma unroll
        for (int ni = 0; ni < 8; ++ni) {
            oacc[ni][0] *= c0; oacc[ni][1] *= c0;
            oacc[ni][2] *= c1; oacc[ni][3] *= c1;
        }
        m0 = m0n; m1 = m1n;

        // ---- P = exp(S-m) directly into A-fragment registers ----
        unsigned pa[4][4];
        {
            float ps0 = 0.f, ps1 = 0.f;
            #pragma unroll
            for (int nj = 0; nj < 4; ++nj) {
                float e00 = __expf(sacc[2*nj][0] - m0n);
                float e01 = __expf(sacc[2*nj][1] - m0n);
                float e02 = __expf(sacc[2*nj][2] - m1n);
                float e03 = __expf(sacc[2*nj][3] - m1n);
                float e10 = __expf(sacc[2*nj+1][0] - m0n);
                float e11 = __expf(sacc[2*nj+1][1] - m0n);
                float e12 = __expf(sacc[2*nj+1][2] - m1n);
                float e13 = __expf(sacc[2*nj+1][3] - m1n);
                ps0 += e00 + e01 + e10 + e11;
                ps1 += e02 + e03 + e12 + e13;
                pa[nj][0] = packh2(e00, e01);   // row lg,   k low
                pa[nj][1] = packh2(e02, e03);   // row lg+8, k low
                pa[nj][2] = packh2(e10, e11);   // row lg,   k high
                pa[nj][3] = packh2(e12, e13);   // row lg+8, k high
            }
            l0 += ps0; l1 += ps1;
        }

        // ---- wait V(kt): leave K(kt+1) in flight when present ----
        if (kt < qt) cpwait<1>(); else cpwait<0>();
        __syncthreads();

        // ---- O += P V  (32 mmas, V via ldmatrix.trans) ----
        #pragma unroll
        for (int nj = 0; nj < 4; ++nj) {
            unsigned vb[8][2];
            #pragma unroll
            for (int ni = 0; ni < 8; ++ni)
                ldsm_x2_t(vb[ni], vfrag + (uint32_t)nj * (16 * AST * 2) + ni * 16);
            #pragma unroll
            for (int ni = 0; ni < 8; ++ni)
                mma_f16(oacc[ni], pa[nj], vb[ni]);
        }
        // no extra barrier: next tile-top cpwait<0> + __syncthreads protects Vs
    }

    // ---- finalize ----
    l0 += __shfl_xor_sync(0xffffffffu, l0, 1);
    l0 += __shfl_xor_sync(0xffffffffu, l0, 2);
    l1 += __shfl_xor_sync(0xffffffffu, l1, 1);
    l1 += __shfl_xor_sync(0xffffffffu, l1, 2);
    float inv0 = 1.f / l0, inv1 = 1.f / l1;

    int r0 = qt * 64 + w * 16 + lg;
    #pragma unroll
    for (int ni = 0; ni < 8; ++ni) {
        int c = ni * 8 + 2 * lt;
        *(__half2*)(O + base + (size_t)r0 * DIM + c) =
            __floats2half2_rn(oacc[ni][0] * inv0, oacc[ni][1] * inv0);
        *(__half2*)(O + base + (size_t)(r0 + 8) * DIM + c) =
            __floats2half2_rn(oacc[ni][2] * inv1, oacc[ni][3] * inv1);
    }
}

// ---------------- launch ------------------------------------------------
extern "C" void kernel_launch(void* const* d_in, const int* in_sizes, int n_in,
                              void* d_out, int out_size)
{
    const float* x     = (const float*)d_in[0];
    const float* wq    = (const float*)d_in[1];
    const float* wk    = (const float*)d_in[2];
    const float* wv    = (const float*)d_in[3];
    const float* wo    = (const float*)d_in[4];
    const float* bo    = (const float*)d_in[5];
    const float* w1    = (const float*)d_in[6];
    const float* b1    = (const float*)d_in[7];
    const float* w2    = (const float*)d_in[8];
    const float* b2    = (const float*)d_in[9];
    const float* gln1  = (const float*)d_in[10];
    const float* bln1  = (const float*)d_in[11];
    const float* gln2  = (const float*)d_in[12];
    const float* bln2  = (const float*)d_in[13];
    float* out = (float*)d_out;

    __half *p_h, *p_q, *p_k, *p_v, *p_attn, *p_ff;
    __half *p_wq, *p_wk, *p_wv, *p_wo, *p_w1, *p_w2;
    float  *p_x1;
    cudaGetSymbolAddress((void**)&p_h,    g_h);
    cudaGetSymbolAddress((void**)&p_q,    g_q);
    cudaGetSymbolAddress((void**)&p_k,    g_k);
    cudaGetSymbolAddress((void**)&p_v,    g_v);
    cudaGetSymbolAddress((void**)&p_attn, g_attn);
    cudaGetSymbolAddress((void**)&p_x1,   g_x1);
    cudaGetSymbolAddress((void**)&p_ff,   g_ff);
    cudaGetSymbolAddress((void**)&p_wq,   g_wq_t);
    cudaGetSymbolAddress((void**)&p_wk,   g_wk_t);
    cudaGetSymbolAddress((void**)&p_wv,   g_wv_t);
    cudaGetSymbolAddress((void**)&p_wo,   g_wo_t);
    cudaGetSymbolAddress((void**)&p_w1,   g_w1_t);
    cudaGetSymbolAddress((void**)&p_w2,   g_w2_t);

    static bool attr_done = false;
    if (!attr_done) {
        cudaFuncSetAttribute(gemm_h<false,false,false,2>,
            cudaFuncAttributeMaxDynamicSharedMemorySize, GEMM_SMEM);
        cudaFuncSetAttribute(gemm_h<true,true,false,0>,
            cudaFuncAttributeMaxDynamicSharedMemorySize, GEMM_SMEM);
        cudaFuncSetAttribute(gemm_h<true,false,true,2>,
            cudaFuncAttributeMaxDynamicSharedMemorySize, GEMM_SMEM);
        attr_done = true;
    }

    dim3 gD(DIM / 128, MROWS / 128);   // (8, 64)
    dim3 gF(FFD / 128, MROWS / 128);   // (32, 64)

    // 0) transpose + fp16-convert all weights (4 DxD in one launch)
    trh4_kernel<<<dim3(DIM/32, DIM/32, 4), 256>>>(
        wq, p_wq, wk, p_wk, wv, p_wv, wo, p_wo);
    trh_kernel<<<dim3(FFD/32, DIM/32), 256>>>(w1, p_w1, DIM, FFD);
    trh_kernel<<<dim3(DIM/32, FFD/32), 256>>>(w2, p_w2, FFD, DIM);

    // 1) h = ln1(x)
    ln_kernel<<<MROWS, 256>>>(x, gln1, bln1, p_h);
    // 2) q,k,v = h @ W{q,k,v}  (fp16 outputs)
    gemm_h<false,false,false,2><<<gD, 256, GEMM_SMEM>>>(p_h, p_wq, nullptr, nullptr, p_q, MROWS, DIM, DIM);
    gemm_h<false,false,false,2><<<gD, 256, GEMM_SMEM>>>(p_h, p_wk, nullptr, nullptr, p_k, MROWS, DIM, DIM);
    gemm_h<false,false,false,2><<<gD, 256, GEMM_SMEM>>>(p_h, p_wv, nullptr, nullptr, p_v, MROWS, DIM, DIM);
    // 3) causal attention (fp16 mma; 64-query tiles; fp16 output)
    attn_h<<<dim3(SEQ / 64, NHEAD, BATCH), 128>>>(p_q, p_k, p_v, p_attn);
    // 4) x1 = x + attn @ wo + bo   (fp32 residual)
    gemm_h<true,true,false,0><<<gD, 256, GEMM_SMEM>>>(p_attn, p_wo, bo, x, p_x1, MROWS, DIM, DIM);
    // 5) h = ln2(x1)
    ln_kernel<<<MROWS, 256>>>(p_x1, gln2, bln2, p_h);
    // 6) ff = relu(h @ w1 + b1)  (fp16 output)
    gemm_h<true,false,true,2><<<gF, 256, GEMM_SMEM>>>(p_h, p_w1, b1, nullptr, p_ff, MROWS, FFD, DIM);
    // 7) out = x1 + ff @ w2 + b2  (fp32 final output)
    gemm_h<true,true,false,0><<<gD, 256, GEMM_SMEM>>>(p_ff, p_w2, b2, p_x1, out, MROWS, DIM, FFD);
}

// round 17
// speedup vs baseline: 1.0547x; 1.0073x over previous
#include <cuda_runtime.h>
#include <cuda_fp16.h>
#include <cstdint>
#include <cstdio>

// Problem dims (fixed by the reference)
#define BATCH 4
#define SEQ   2048
#define DIM   1024
#define NHEAD 16
#define HDIM  64
#define FFD   4096
#define MROWS (BATCH*SEQ)   // 8192

// ---------------- scratch (static device globals; no runtime alloc) -------
__device__ __half g_h   [(size_t)MROWS * DIM];   // ln out (fp16)
__device__ __half g_q   [(size_t)MROWS * DIM];   // fp16 q/k/v
__device__ __half g_k   [(size_t)MROWS * DIM];
__device__ __half g_v   [(size_t)MROWS * DIM];
__device__ __half g_attn[(size_t)MROWS * DIM];   // fp16 (feeds WO gemm)
__device__ float  g_x1  [(size_t)MROWS * DIM];   // fp32 residual
__device__ __half g_ff  [(size_t)MROWS * FFD];   // fp16 (feeds FF2 gemm)
// transposed + fp16 weight copies  WT[n][k] = half(W[k][n])
__device__ __half g_wq_t[(size_t)DIM * DIM];
__device__ __half g_wk_t[(size_t)DIM * DIM];
__device__ __half g_wv_t[(size_t)DIM * DIM];
__device__ __half g_wo_t[(size_t)DIM * DIM];
__device__ __half g_w1_t[(size_t)DIM * FFD];   // [4096][1024]
__device__ __half g_w2_t[(size_t)FFD * DIM];   // [1024][4096]

// ---------------- helpers -------------------------------------------------
// fp16 mma (fp32 accumulate)
__device__ __forceinline__ void mma_f16(float* c, const unsigned* a, const unsigned* b) {
    asm volatile(
        "mma.sync.aligned.m16n8k16.row.col.f32.f16.f16.f32 "
        "{%0,%1,%2,%3}, {%4,%5,%6,%7}, {%8,%9}, {%0,%1,%2,%3};"
        : "+f"(c[0]), "+f"(c[1]), "+f"(c[2]), "+f"(c[3])
        : "r"(a[0]), "r"(a[1]), "r"(a[2]), "r"(a[3]), "r"(b[0]), "r"(b[1]));
}
__device__ __forceinline__ void ldsm_x4(unsigned* r, uint32_t addr) {
    asm volatile("ldmatrix.sync.aligned.m8n8.x4.shared.b16 {%0,%1,%2,%3}, [%4];"
        : "=r"(r[0]), "=r"(r[1]), "=r"(r[2]), "=r"(r[3]) : "r"(addr));
}
__device__ __forceinline__ void ldsm_x2(unsigned* r, uint32_t addr) {
    asm volatile("ldmatrix.sync.aligned.m8n8.x2.shared.b16 {%0,%1}, [%2];"
        : "=r"(r[0]), "=r"(r[1]) : "r"(addr));
}
__device__ __forceinline__ void ldsm_x4_t(unsigned* r, uint32_t addr) {
    asm volatile("ldmatrix.sync.aligned.m8n8.x4.trans.shared.b16 {%0,%1,%2,%3}, [%4];"
        : "=r"(r[0]), "=r"(r[1]), "=r"(r[2]), "=r"(r[3]) : "r"(addr));
}
__device__ __forceinline__ unsigned packh2(float a, float b) {
    __half2 h = __floats2half2_rn(a, b);
    return *(unsigned*)&h;
}
__device__ __forceinline__ void cpasync16(void* smem, const void* gmem) {
    unsigned s = (unsigned)__cvta_generic_to_shared(smem);
    asm volatile("cp.async.cg.shared.global [%0], [%1], 16;" :: "r"(s), "l"(gmem));
}
__device__ __forceinline__ void cpcommit() {
    asm volatile("cp.async.commit_group;");
}
template<int N> __device__ __forceinline__ void cpwait() {
    asm volatile("cp.async.wait_group %0;" :: "n"(N));
}
__device__ __forceinline__ uint32_t smem_u32(const void* p) {
    return (uint32_t)__cvta_generic_to_shared(p);
}

// ---------------- weight transpose + fp16 convert -------------------------
// S[R][C] float -> D[C][R] half (one matrix)
__global__ __launch_bounds__(256) void trh_kernel(
    const float* __restrict__ S, __half* __restrict__ D, int R, int C)
{
    __shared__ float t[32][33];
    int bx = blockIdx.x * 32;
    int by = blockIdx.y * 32;
    int tx = threadIdx.x & 31, ty = threadIdx.x >> 5;
    #pragma unroll
    for (int i = 0; i < 4; ++i) {
        int r = by + ty + i * 8;
        t[ty + i * 8][tx] = S[(size_t)r * C + bx + tx];
    }
    __syncthreads();
    #pragma unroll
    for (int i = 0; i < 4; ++i) {
        int r = bx + ty + i * 8;
        D[(size_t)r * R + by + tx] = __float2half(t[tx][ty + i * 8]);
    }
}

// batched version for the 4 DxD matrices (wq, wk, wv, wo)
__global__ __launch_bounds__(256) void trh4_kernel(
    const float* __restrict__ s0, __half* __restrict__ d0,
    const float* __restrict__ s1, __half* __restrict__ d1,
    const float* __restrict__ s2, __half* __restrict__ d2,
    const float* __restrict__ s3, __half* __restrict__ d3)
{
    const float* S; __half* D;
    switch (blockIdx.z) {
        case 0: S = s0; D = d0; break;
        case 1: S = s1; D = d1; break;
        case 2: S = s2; D = d2; break;
        default:S = s3; D = d3; break;
    }
    __shared__ float t[32][33];
    int bx = blockIdx.x * 32;
    int by = blockIdx.y * 32;
    int tx = threadIdx.x & 31, ty = threadIdx.x >> 5;
    #pragma unroll
    for (int i = 0; i < 4; ++i) {
        int r = by + ty + i * 8;
        t[ty + i * 8][tx] = S[(size_t)r * DIM + bx + tx];
    }
    __syncthreads();
    #pragma unroll
    for (int i = 0; i < 4; ++i) {
        int r = bx + ty + i * 8;
        D[(size_t)r * DIM + by + tx] = __float2half(t[tx][ty + i * 8]);
    }
}

// ---------------- layernorm (fp16 output) ---------------------------------
__global__ __launch_bounds__(256) void ln_kernel(
    const float* __restrict__ X, const float* __restrict__ gamma,
    const float* __restrict__ beta, __half* __restrict__ Y)
{
    int row = blockIdx.x;
    const float* x = X + (size_t)row * DIM;
    float4 v = *(const float4*)(x + threadIdx.x * 4);
    float s  = v.x + v.y + v.z + v.w;
    float ss = v.x*v.x + v.y*v.y + v.z*v.z + v.w*v.w;

    #pragma unroll
    for (int o = 16; o; o >>= 1) {
        s  += __shfl_xor_sync(0xffffffffu, s, o);
        ss += __shfl_xor_sync(0xffffffffu, ss, o);
    }
    __shared__ float sw[8], ssw[8], bc[2];
    int w = threadIdx.x >> 5, lane = threadIdx.x & 31;
    if (lane == 0) { sw[w] = s; ssw[w] = ss; }
    __syncthreads();
    if (threadIdx.x == 0) {
        float S = 0.f, SS = 0.f;
        #pragma unroll
        for (int i = 0; i < 8; ++i) { S += sw[i]; SS += ssw[i]; }
        float mu  = S * (1.f / DIM);
        float var = SS * (1.f / DIM) - mu * mu;
        bc[0] = mu;
        bc[1] = rsqrtf(var + 1e-5f);
    }
    __syncthreads();
    float mu = bc[0], r = bc[1];
    float4 gv = *(const float4*)(gamma + threadIdx.x * 4);
    float4 bv = *(const float4*)(beta  + threadIdx.x * 4);
    __half* yp = Y + (size_t)row * DIM + threadIdx.x * 4;
    *(__half2*)(yp)     = __floats2half2_rn((v.x - mu) * r * gv.x + bv.x,
                                            (v.y - mu) * r * gv.y + bv.y);
    *(__half2*)(yp + 2) = __floats2half2_rn((v.z - mu) * r * gv.z + bv.z,
                                            (v.w - mu) * r * gv.w + bv.w);
}

// ---------------- fp16 tensor-core GEMM, 3-stage cp.async, BK=64 ----------
// C[M,N] = A[M,K] @ BT[N,K]^T (+bias)(+res)(relu); OUT: 0=f32, 2=f16
// B fragments fetched two n-groups at a time via ldmatrix.x4.
constexpr int HSTRIDE = 72;                       // halfs per smem row (64+8 pad)
constexpr int ASZH = 128 * HSTRIDE;               // 9216 halfs per A stage
constexpr int STGH = 2 * ASZH;                    // halfs per stage (A+B)
constexpr int GEMM_SMEM = 3 * STGH * 2;           // 110592 bytes

__device__ __forceinline__ void load_tile_h(
    __half* sA, __half* sB, const __half* Ablk, const __half* Bblk,
    int k0, int K, int tid)
{
    // A tile: 128 rows x 64 halfs = 1024 16B-chunks; 4 per thread
    #pragma unroll
    for (int it = 0; it < 4; ++it) {
        int i = tid + it * 256;
        int r = i >> 3, c = i & 7;
        cpasync16(sA + r * HSTRIDE + c * 8, Ablk + (size_t)r * K + k0 + c * 8);
    }
    #pragma unroll
    for (int it = 0; it < 4; ++it) {
        int i = tid + it * 256;
        int r = i >> 3, c = i & 7;
        cpasync16(sB + r * HSTRIDE + c * 8, Bblk + (size_t)r * K + k0 + c * 8);
    }
}

template<bool HAS_BIAS, bool HAS_RES, bool RELU, int OUT>
__global__ __launch_bounds__(256, 2) void gemm_h(
    const __half* __restrict__ A, const __half* __restrict__ BT,
    const float* __restrict__ bias, const float* __restrict__ Res,
    void* __restrict__ Cv, int M, int N, int K)
{
    extern __shared__ __half smem[];

    int tid  = threadIdx.x;
    int warp = tid >> 5, lane = tid & 31;
    int wm = (warp >> 2) * 64;
    int wn = (warp & 3) * 32;
    int lg = lane >> 2;
    int lt = lane & 3;
    int bm = blockIdx.y, bn = blockIdx.x;

    const __half* Ablk = A  + (size_t)bm * 128 * K;
    const __half* Bblk = BT + (size_t)bn * 128 * K;

    uint32_t base_u = smem_u32(smem);
    uint32_t a_off = (uint32_t)(wm + (lane & 15)) * 144 + ((lane >> 4) & 1) * 16;
    // B x4 layout: lanes 0-7 row n..n+7 (k lo), 8-15 same rows (k hi),
    //              16-23 rows n+8..n+15 (k lo), 24-31 (k hi)
    uint32_t b_off = (uint32_t)(128 + wn + (lane & 7) + ((lane >> 4) & 1) * 8) * 144
                   + ((lane >> 3) & 1) * 16;

    float acc[4][4][4] = {};

    load_tile_h(smem, smem + ASZH, Ablk, Bblk, 0, K, tid);
    cpcommit();
    load_tile_h(smem + STGH, smem + STGH + ASZH, Ablk, Bblk, 64, K, tid);
    cpcommit();

    int T = K / 64;
    int s = 0;
    for (int t = 0; t < T; ++t) {
        cpwait<1>();
        __syncthreads();
        uint32_t stage_u = base_u + s * (STGH * 2);

        #pragma unroll
        for (int ks = 0; ks < 4; ++ks) {
            unsigned a[4][4], b[4][2];
            #pragma unroll
            for (int mi = 0; mi < 4; ++mi)
                ldsm_x4(a[mi], stage_u + a_off + mi * (16 * 144) + ks * 32);
            #pragma unroll
            for (int nj = 0; nj < 2; ++nj) {
                unsigned bq[4];
                ldsm_x4(bq, stage_u + b_off + nj * (16 * 144) + ks * 32);
                b[2 * nj][0]     = bq[0];
                b[2 * nj][1]     = bq[1];
                b[2 * nj + 1][0] = bq[2];
                b[2 * nj + 1][1] = bq[3];
            }
            #pragma unroll
            for (int mi = 0; mi < 4; ++mi)
                #pragma unroll
                for (int ni = 0; ni < 4; ++ni)
                    mma_f16(acc[mi][ni], a[mi], b[ni]);
        }
        int nt = t + 2;
        if (nt < T) {
            int sn = nt % 3;
            load_tile_h(smem + sn * STGH, smem + sn * STGH + ASZH,
                        Ablk, Bblk, nt * 64, K, tid);
        }
        cpcommit();
        s = (s + 1 == 3) ? 0 : s + 1;
    }

    #pragma unroll
    for (int mi = 0; mi < 4; ++mi) {
        int r0 = bm * 128 + wm + mi * 16 + lg;
        #pragma unroll
        for (int ni = 0; ni < 4; ++ni) {
            int c0 = bn * 128 + wn + ni * 8 + lt * 2;
            #pragma unroll
            for (int half_i = 0; half_i < 2; ++half_i) {
                int row = r0 + half_i * 8;
                float2 o;
                o.x = acc[mi][ni][half_i * 2 + 0];
                o.y = acc[mi][ni][half_i * 2 + 1];
                if (HAS_BIAS) { o.x += bias[c0]; o.y += bias[c0 + 1]; }
                if (HAS_RES) {
                    float2 rr = *(const float2*)(Res + (size_t)row * N + c0);
                    o.x += rr.x; o.y += rr.y;
                }
                if (RELU) { o.x = fmaxf(o.x, 0.f); o.y = fmaxf(o.y, 0.f); }
                if (OUT == 2) {
                    *(__half2*)((__half*)Cv + (size_t)row * N + c0) =
                        __floats2half2_rn(o.x, o.y);
                } else {
                    *(float2*)((float*)Cv + (size_t)row * N + c0) = o;
                }
            }
        }
    }
}

// ---------------- fp16 tensor-core causal flash attention -----------------
// 128 threads = 4 warps; warp w owns query rows [w*16, w*16+16).
// K double-buffered via cp.async; V single buffer awaited pre-PV.
// K fragments via ldmatrix.x4 (two n-groups), V via ldmatrix.x4.trans
// (two 8-col n-groups) — same register values as the x2 pairs.
constexpr int AST = 72;   // halfs per attn smem row (144B) — conflict-free ldsm

__global__ __launch_bounds__(128) void attn_h(
    const __half* __restrict__ Q, const __half* __restrict__ Kg,
    const __half* __restrict__ Vg, __half* __restrict__ O)
{
    __shared__ __half Qs[64][AST];
    __shared__ __half Ks[2][64][AST];
    __shared__ __half Vs[64][AST];

    int tid = threadIdx.x;
    int w = tid >> 5, lane = tid & 31;
    int lg = lane >> 2, lt = lane & 3;
    int qt = blockIdx.x, h = blockIdx.y, b = blockIdx.z;
    size_t base = ((size_t)b * SEQ) * DIM + h * HDIM;

    // ---- prefetch K tile 0 (async) ----
    #pragma unroll
    for (int it = 0; it < 4; ++it) {
        int i = tid + it * 128;
        int r = i >> 3, c = i & 7;
        cpasync16(&Ks[0][r][c * 8], Kg + base + (size_t)r * DIM + c * 8);
    }
    cpcommit();

    // ---- stage Q tile (scaled by 1/8, exact in fp16) ----
    {
        __half2 sc = __half2half2(__float2half(0.125f));
        #pragma unroll
        for (int it = 0; it < 4; ++it) {
            int i = tid + it * 128;
            int r = i >> 3, c = i & 7;
            uint4 raw = *(const uint4*)(Q + base + (size_t)(qt * 64 + r) * DIM + c * 8);
            __half2* hp = (__half2*)&raw;
            hp[0] = __hmul2(hp[0], sc); hp[1] = __hmul2(hp[1], sc);
            hp[2] = __hmul2(hp[2], sc); hp[3] = __hmul2(hp[3], sc);
            *(uint4*)&Qs[r][c * 8] = raw;
        }
    }
    __syncthreads();
    unsigned qa[4][4];
    {
        uint32_t qaddr = smem_u32(&Qs[0][0])
                       + (uint32_t)(w * 16 + (lane & 15)) * (AST * 2)
                       + ((lane >> 4) & 1) * 16;
        #pragma unroll
        for (int ks = 0; ks < 4; ++ks) ldsm_x4(qa[ks], qaddr + ks * 32);
    }

    uint32_t v_base = smem_u32(&Vs[0][0]);
    // V x4.trans: lanes 0-15 rows r (cols ni*8), lanes 16-31 same rows cols +8
    uint32_t vfrag = v_base + (uint32_t)(lane & 15) * (AST * 2)
                   + ((lane >> 4) & 1) * 16;

    float m0 = -1e30f, m1 = -1e30f, l0 = 0.f, l1 = 0.f;
    float oacc[8][4] = {};

    for (int kt = 0; kt <= qt; ++kt) {
        int cur = kt & 1;
        // ---- wait K(kt) (only pending group), barrier also frees Vs ----
        cpwait<0>();
        __syncthreads();

        // ---- issue V(kt) async (consumed after softmax) ----
        #pragma unroll
        for (int it = 0; it < 4; ++it) {
            int i = tid + it * 128;
            int r = i >> 3, c = i & 7;
            cpasync16(&Vs[r][c * 8],
                      Vg + base + (size_t)(kt * 64 + r) * DIM + c * 8);
        }
        cpcommit();

        // K x4: lanes 0-7 rows n..n+7 (k lo), 8-15 (k hi), 16-31 rows n+8..n+15
        uint32_t kfrag = smem_u32(&Ks[cur][0][0])
                       + (uint32_t)((lane & 7) + ((lane >> 4) & 1) * 8) * (AST * 2)
                       + ((lane >> 3) & 1) * 16;

        // ---- S = Q K^T (16x64 per warp), 32 mmas ----
        float sacc[8][4] = {};
        #pragma unroll
        for (int ks = 0; ks < 4; ++ks) {
            unsigned bf[8][2];
            #pragma unroll
            for (int nj = 0; nj < 4; ++nj) {
                unsigned bq[4];
                ldsm_x4(bq, kfrag + (uint32_t)nj * (16 * AST * 2) + ks * 32);
                bf[2 * nj][0]     = bq[0];
                bf[2 * nj][1]     = bq[1];
                bf[2 * nj + 1][0] = bq[2];
                bf[2 * nj + 1][1] = bq[3];
            }
            #pragma unroll
            for (int ni = 0; ni < 8; ++ni)
                mma_f16(sacc[ni], qa[ks], bf[ni]);
        }

        // ---- prefetch K(kt+1) into the other buffer ----
        if (kt < qt) {
            int nb = cur ^ 1;
            #pragma unroll
            for (int it = 0; it < 4; ++it) {
                int i = tid + it * 128;
                int r = i >> 3, c = i & 7;
                cpasync16(&Ks[nb][r][c * 8],
                          Kg + base + (size_t)((kt + 1) * 64 + r) * DIM + c * 8);
            }
            cpcommit();
        }

        // ---- causal mask (diagonal tile only) ----
        if (kt == qt) {
            int rq0 = w * 16 + lg, rq1 = rq0 + 8;
            #pragma unroll
            for (int ni = 0; ni < 8; ++ni) {
                int j0 = ni * 8 + 2 * lt, j1 = j0 + 1;
                if (j0 > rq0) sacc[ni][0] = -1e30f;
                if (j1 > rq0) sacc[ni][1] = -1e30f;
                if (j0 > rq1) sacc[ni][2] = -1e30f;
                if (j1 > rq1) sacc[ni][3] = -1e30f;
            }
        }

        // ---- online softmax ----
        float mx0 = -1e30f, mx1 = -1e30f;
        #pragma unroll
        for (int ni = 0; ni < 8; ++ni) {
            mx0 = fmaxf(mx0, fmaxf(sacc[ni][0], sacc[ni][1]));
            mx1 = fmaxf(mx1, fmaxf(sacc[ni][2], sacc[ni][3]));
        }
        mx0 = fmaxf(mx0, __shfl_xor_sync(0xffffffffu, mx0, 1));
        mx0 = fmaxf(mx0, __shfl_xor_sync(0xffffffffu, mx0, 2));
        mx1 = fmaxf(mx1, __shfl_xor_sync(0xffffffffu, mx1, 1));
        mx1 = fmaxf(mx1, __shfl_xor_sync(0xffffffffu, mx1, 2));
        float m0n = fmaxf(m0, mx0), m1n = fmaxf(m1, mx1);
        float c0 = __expf(m0 - m0n), c1 = __expf(m1 - m1n);
        l0 *= c0; l1 *= c1;
        #pragma unroll
        for (int ni = 0; ni < 8; ++ni) {
            oacc[ni][0] *= c0; oacc[ni][1] *= c0;
            oacc[ni][2] *= c1; oacc[ni][3] *= c1;
        }
        m0 = m0n; m1 = m1n;

        // ---- P = exp(S-m) directly into A-fragment registers ----
        unsigned pa[4][4];
        {
            float ps0 = 0.f, ps1 = 0.f;
            #pragma unroll
            for (int nj = 0; nj < 4; ++nj) {
                float e00 = __expf(sacc[2*nj][0] - m0n);
                float e01 = __expf(sacc[2*nj][1] - m0n);
                float e02 = __expf(sacc[2*nj][2] - m1n);
                float e03 = __expf(sacc[2*nj][3] - m1n);
                float e10 = __expf(sacc[2*nj+1][0] - m0n);
                float e11 = __expf(sacc[2*nj+1][1] - m0n);
                float e12 = __expf(sacc[2*nj+1][2] - m1n);
                float e13 = __expf(sacc[2*nj+1][3] - m1n);
                ps0 += e00 + e01 + e10 + e11;
                ps1 += e02 + e03 + e12 + e13;
                pa[nj][0] = packh2(e00, e01);   // row lg,   k low
                pa[nj][1] = packh2(e02, e03);   // row lg+8, k low
                pa[nj][2] = packh2(e10, e11);   // row lg,   k high
                pa[nj][3] = packh2(e12, e13);   // row lg+8, k high
            }
            l0 += ps0; l1 += ps1;
        }

        // ---- wait V(kt): leave K(kt+1) in flight when present ----
        if (kt < qt) cpwait<1>(); else cpwait<0>();
        __syncthreads();

        // ---- O += P V  (32 mmas, V via ldmatrix.x4.trans) ----
        #pragma unroll
        for (int nj = 0; nj < 4; ++nj) {
            unsigned vb[8][2];
            #pragma unroll
            for (int np = 0; np < 4; ++np) {
                unsigned vq[4];
                ldsm_x4_t(vq, vfrag + (uint32_t)nj * (16 * AST * 2) + np * 32);
                vb[2 * np][0]     = vq[0];
                vb[2 * np][1]     = vq[1];
                vb[2 * np + 1][0] = vq[2];
                vb[2 * np + 1][1] = vq[3];
            }
            #pragma unroll
            for (int ni = 0; ni < 8; ++ni)
                mma_f16(oacc[ni], pa[nj], vb[ni]);
        }
        // no extra barrier: next tile-top cpwait<0> + __syncthreads protects Vs
    }

    // ---- finalize ----
    l0 += __shfl_xor_sync(0xffffffffu, l0, 1);
    l0 += __shfl_xor_sync(0xffffffffu, l0, 2);
    l1 += __shfl_xor_sync(0xffffffffu, l1, 1);
    l1 += __shfl_xor_sync(0xffffffffu, l1, 2);
    float inv0 = 1.f / l0, inv1 = 1.f / l1;

    int r0 = qt * 64 + w * 16 + lg;
    #pragma unroll
    for (int ni = 0; ni < 8; ++ni) {
        int c = ni * 8 + 2 * lt;
        *(__half2*)(O + base + (size_t)r0 * DIM + c) =
            __floats2half2_rn(oacc[ni][0] * inv0, oacc[ni][1] * inv0);
        *(__half2*)(O + base + (size_t)(r0 + 8) * DIM + c) =
            __floats2half2_rn(oacc[ni][2] * inv1, oacc[ni][3] * inv1);
    }
}

// ---------------- launch ------------------------------------------------
extern "C" void kernel_launch(void* const* d_in, const int* in_sizes, int n_in,
                              void* d_out, int out_size)
{
    const float* x     = (const float*)d_in[0];
    const float* wq    = (const float*)d_in[1];
    const float* wk    = (const float*)d_in[2];
    const float* wv    = (const float*)d_in[3];
    const float* wo    = (const float*)d_in[4];
    const float* bo    = (const float*)d_in[5];
    const float* w1    = (const float*)d_in[6];
    const float* b1    = (const float*)d_in[7];
    const float* w2    = (const float*)d_in[8];
    const float* b2    = (const float*)d_in[9];
    const float* gln1  = (const float*)d_in[10];
    const float* bln1  = (const float*)d_in[11];
    const float* gln2  = (const float*)d_in[12];
    const float* bln2  = (const float*)d_in[13];
    float* out = (float*)d_out;

    __half *p_h, *p_q, *p_k, *p_v, *p_attn, *p_ff;
    __half *p_wq, *p_wk, *p_wv, *p_wo, *p_w1, *p_w2;
    float  *p_x1;
    cudaGetSymbolAddress((void**)&p_h,    g_h);
    cudaGetSymbolAddress((void**)&p_q,    g_q);
    cudaGetSymbolAddress((void**)&p_k,    g_k);
    cudaGetSymbolAddress((void**)&p_v,    g_v);
    cudaGetSymbolAddress((void**)&p_attn, g_attn);
    cudaGetSymbolAddress((void**)&p_x1,   g_x1);
    cudaGetSymbolAddress((void**)&p_ff,   g_ff);
    cudaGetSymbolAddress((void**)&p_wq,   g_wq_t);
    cudaGetSymbolAddress((void**)&p_wk,   g_wk_t);
    cudaGetSymbolAddress((void**)&p_wv,   g_wv_t);
    cudaGetSymbolAddress((void**)&p_wo,   g_wo_t);
    cudaGetSymbolAddress((void**)&p_w1,   g_w1_t);
    cudaGetSymbolAddress((void**)&p_w2,   g_w2_t);

    static bool attr_done = false;
    if (!attr_done) {
        cudaFuncSetAttribute(gemm_h<false,false,false,2>,
            cudaFuncAttributeMaxDynamicSharedMemorySize, GEMM_SMEM);
        cudaFuncSetAttribute(gemm_h<true,true,false,0>,
            cudaFuncAttributeMaxDynamicSharedMemorySize, GEMM_SMEM);
        cudaFuncSetAttribute(gemm_h<true,false,true,2>,
            cudaFuncAttributeMaxDynamicSharedMemorySize, GEMM_SMEM);
        attr_done = true;
    }

    dim3 gD(DIM / 128, MROWS / 128);   // (8, 64)
    dim3 gF(FFD / 128, MROWS / 128);   // (32, 64)

    // 0) transpose + fp16-convert all weights (4 DxD in one launch)
    trh4_kernel<<<dim3(DIM/32, DIM/32, 4), 256>>>(
        wq, p_wq, wk, p_wk, wv, p_wv, wo, p_wo);
    trh_kernel<<<dim3(FFD/32, DIM/32), 256>>>(w1, p_w1, DIM, FFD);
    trh_kernel<<<dim3(DIM/32, FFD/32), 256>>>(w2, p_w2, FFD, DIM);

    // 1) h = ln1(x)
    ln_kernel<<<MROWS, 256>>>(x, gln1, bln1, p_h);
    // 2) q,k,v = h @ W{q,k,v}  (fp16 outputs)
    gemm_h<false,false,false,2><<<gD, 256, GEMM_SMEM>>>(p_h, p_wq, nullptr, nullptr, p_q, MROWS, DIM, DIM);
    gemm_h<false,false,false,2><<<gD, 256, GEMM_SMEM>>>(p_h, p_wk, nullptr, nullptr, p_k, MROWS, DIM, DIM);
    gemm_h<false,false,false,2><<<gD, 256, GEMM_SMEM>>>(p_h, p_wv, nullptr, nullptr, p_v, MROWS, DIM, DIM);
    // 3) causal attention (fp16 mma; 64-query tiles; fp16 output)
    attn_h<<<dim3(SEQ / 64, NHEAD, BATCH), 128>>>(p_q, p_k, p_v, p_attn);
    // 4) x1 = x + attn @ wo + bo   (fp32 residual)
    gemm_h<true,true,false,0><<<gD, 256, GEMM_SMEM>>>(p_attn, p_wo, bo, x, p_x1, MROWS, DIM, DIM);
    // 5) h = ln2(x1)
    ln_kernel<<<MROWS, 256>>>(p_x1, gln2, bln2, p_h);
    // 6) ff = relu(h @ w1 + b1)  (fp16 output)
    gemm_h<true,false,true,2><<<gF, 256, GEMM_SMEM>>>(p_h, p_w1, b1, nullptr, p_ff, MROWS, FFD, DIM);
    // 7) out = x1 + ff @ w2 + b2  (fp32 final output)
    gemm_h<true,true,false,0><<<gD, 256, GEMM_SMEM>>>(p_ff, p_w2, b2, p_x1, out, MROWS, DIM, FFD);
}